// round 15
// baseline (speedup 1.0000x reference)
#include <cuda_runtime.h>

// Problem constants
#define Bn 8
#define Tn 2048
#define Cn 1024
#define Hn 64
#define Mn (Bn * Tn)   // 16384 rows

// Scratch for Q, K, V projections (device globals: no runtime allocation)
__device__ float g_Q[(size_t)Mn * Hn];
__device__ float g_K[(size_t)Mn * Hn];
__device__ float g_V[(size_t)Mn * Hn];

// ---------------------------------------------------------------------------
// Helpers
// ---------------------------------------------------------------------------
__device__ __forceinline__ float f2tf(float f) {
    unsigned u;
    asm("cvt.rna.tf32.f32 %0, %1;" : "=r"(u) : "f"(f));
    return __uint_as_float(u);
}

__device__ __forceinline__ void mma_tf32(float& d0, float& d1, float& d2, float& d3,
                                         unsigned a0, unsigned a1, unsigned a2, unsigned a3,
                                         unsigned b0, unsigned b1)
{
    asm volatile(
        "mma.sync.aligned.m16n8k8.row.col.f32.tf32.tf32.f32 "
        "{%0,%1,%2,%3}, {%4,%5,%6,%7}, {%8,%9}, {%0,%1,%2,%3};\n"
        : "+f"(d0), "+f"(d1), "+f"(d2), "+f"(d3)
        : "r"(a0), "r"(a1), "r"(a2), "r"(a3), "r"(b0), "r"(b1));
}

// k16-chunk swizzled smem index: tile row `row`, k = c4 + 4*k4 within chunk.
// Layout row*16 + ((c4 ^ (row&3))<<2) + k4  -> LDS.128 at (row, c4) is
// conflict-free across the 8-thread phases of a warp fragment load.
__device__ __forceinline__ int swz(int row, int c4, int k4) {
    return row * 16 + (((c4 ^ (row & 3))) << 2) + k4;
}

// ---------------------------------------------------------------------------
// Kernel 1: fused QKV projection via tf32 mma.
// C[16384 x 192] = x[16384 x 1024] @ [Wq|Wk|Wv], Q scaled by 1/8.
// BM=64, BN=192, BK=16, 256 threads = 8 warps as 2(m) x 4(n), warp tile 32x48.
// Double-buffered smem, tf32 conversion at STS.
// ---------------------------------------------------------------------------
__global__ __launch_bounds__(256, 2)
void qkv_mma(const float* __restrict__ x, const float* __restrict__ Wq,
             const float* __restrict__ Wk, const float* __restrict__ Wv)
{
    __shared__ __align__(16) float As[2][64 * 16];
    __shared__ __align__(16) float Bs[2][192 * 16];

    const int t    = threadIdx.x;
    const int lane = t & 31;
    const int warp = t >> 5;
    const int g    = lane >> 2;   // group 0..7
    const int q4   = lane & 3;    // 0..3
    const int wm   = warp >> 2;   // 0..1
    const int wn   = warp & 3;    // 0..3
    const int m0   = blockIdx.x * 64;

    // A gmem assignment: thread -> (row = t/4, k-quad u = t%4)
    const int arow = t >> 2;
    const int au   = t & 3;
    const float* aptr = x + (size_t)(m0 + arow) * Cn + au * 4;

    // B gmem assignment: 768 float4 per tile, 3 per thread
    int bk[3], bn[3];
    const float* bp[3];
#pragma unroll
    for (int r = 0; r < 3; ++r) {
        int f  = t + 256 * r;
        int k  = f / 48;
        int n  = (f % 48) * 4;
        bk[r] = k; bn[r] = n;
        const float* W = (n < 64) ? Wq : (n < 128) ? Wk : Wv;
        bp[r] = W + (size_t)k * Hn + (n & 63);
    }

    float acc[2][6][4];
#pragma unroll
    for (int i = 0; i < 2; ++i)
#pragma unroll
        for (int j = 0; j < 6; ++j)
#pragma unroll
            for (int e = 0; e < 4; ++e) acc[i][j][e] = 0.f;

    float4 aR, bR[3];

    // prologue: tile 0
    aR = *(const float4*)aptr;
#pragma unroll
    for (int r = 0; r < 3; ++r) bR[r] = *(const float4*)(bp[r]);
    {
        float av[4] = {aR.x, aR.y, aR.z, aR.w};
#pragma unroll
        for (int e = 0; e < 4; ++e) As[0][swz(arow, e, au)] = f2tf(av[e]);
#pragma unroll
        for (int r = 0; r < 3; ++r) {
            float bv[4] = {bR[r].x, bR[r].y, bR[r].z, bR[r].w};
#pragma unroll
            for (int e = 0; e < 4; ++e)
                Bs[0][swz(bn[r] + e, bk[r] & 3, bk[r] >> 2)] = f2tf(bv[e]);
        }
    }
    __syncthreads();

    for (int it = 0; it < Cn / 16; ++it) {
        const int s = it & 1;
        if (it < Cn / 16 - 1) {
            aR = *(const float4*)(aptr + (it + 1) * 16);
#pragma unroll
            for (int r = 0; r < 3; ++r)
                bR[r] = *(const float4*)(bp[r] + (size_t)(it + 1) * 16 * Hn);
        }

        // A fragments (both k8 steps of the k16 chunk)
        unsigned a[2][2][4];
#pragma unroll
        for (int i = 0; i < 2; ++i) {
            int rA = wm * 32 + 16 * i + g;
            int rB = rA + 8;
            float4 lo = *(const float4*)&As[s][swz(rA, q4, 0)];
            float4 hi = *(const float4*)&As[s][swz(rB, q4, 0)];
            a[i][0][0] = __float_as_uint(lo.x); a[i][0][1] = __float_as_uint(hi.x);
            a[i][0][2] = __float_as_uint(lo.y); a[i][0][3] = __float_as_uint(hi.y);
            a[i][1][0] = __float_as_uint(lo.z); a[i][1][1] = __float_as_uint(hi.z);
            a[i][1][2] = __float_as_uint(lo.w); a[i][1][3] = __float_as_uint(hi.w);
        }
#pragma unroll
        for (int j = 0; j < 6; ++j) {
            int n = wn * 48 + 8 * j + g;
            float4 bv = *(const float4*)&Bs[s][swz(n, q4, 0)];
            unsigned b00 = __float_as_uint(bv.x), b01 = __float_as_uint(bv.y);
            unsigned b10 = __float_as_uint(bv.z), b11 = __float_as_uint(bv.w);
#pragma unroll
            for (int i = 0; i < 2; ++i) {
                mma_tf32(acc[i][j][0], acc[i][j][1], acc[i][j][2], acc[i][j][3],
                         a[i][0][0], a[i][0][1], a[i][0][2], a[i][0][3], b00, b01);
                mma_tf32(acc[i][j][0], acc[i][j][1], acc[i][j][2], acc[i][j][3],
                         a[i][1][0], a[i][1][1], a[i][1][2], a[i][1][3], b10, b11);
            }
        }

        if (it < Cn / 16 - 1) {
            const int d = s ^ 1;
            float av[4] = {aR.x, aR.y, aR.z, aR.w};
#pragma unroll
            for (int e = 0; e < 4; ++e) As[d][swz(arow, e, au)] = f2tf(av[e]);
#pragma unroll
            for (int r = 0; r < 3; ++r) {
                float bv[4] = {bR[r].x, bR[r].y, bR[r].z, bR[r].w};
#pragma unroll
                for (int e = 0; e < 4; ++e)
                    Bs[d][swz(bn[r] + e, bk[r] & 3, bk[r] >> 2)] = f2tf(bv[e]);
            }
        }
        __syncthreads();
    }

    // epilogue: scatter to g_Q (scaled) / g_K / g_V
#pragma unroll
    for (int i = 0; i < 2; ++i) {
        int row = m0 + wm * 32 + 16 * i + g;
#pragma unroll
        for (int j = 0; j < 6; ++j) {
            int nn = wn * 48 + 8 * j;
            float* dst = (nn < 64) ? g_Q : (nn < 128) ? g_K : g_V;
            float sc = (nn < 64) ? 0.125f : 1.0f;
            int col = (nn & 63) + 2 * q4;
            *(float2*)&dst[(size_t)row * Hn + col] =
                make_float2(acc[i][j][0] * sc, acc[i][j][1] * sc);
            *(float2*)&dst[(size_t)(row + 8) * Hn + col] =
                make_float2(acc[i][j][2] * sc, acc[i][j][3] * sc);
        }
    }
}

// ---------------------------------------------------------------------------
// Kernel 2: causal flash attention via tf32 mma.
// Br = Kc = 64, 128 threads = 4 warps, each warp owns 16 full query rows
// (warp S tile 16x64 -> softmax row stats reduce within a quad, 2 shfls).
// Q fragments register-resident; P routed through the freed Q smem buffer
// (warp-local rows -> __syncwarp only). Static smem = 48KB.
// ---------------------------------------------------------------------------
__global__ __launch_bounds__(128, 3)
void attn_mma(float* __restrict__ out)
{
    __shared__ __align__(16) float Ps[64 * 64];  // Q (chunked), then P
    __shared__ __align__(16) float Ks[64 * 64];  // K rows=key, k=embedding
    __shared__ __align__(16) float Vs[64 * 64];  // V^T rows=dim, k=key

    const int t    = threadIdx.x;
    const int lane = t & 31;
    const int warp = t >> 5;
    const int g    = lane >> 2;
    const int q4   = lane & 3;
    const int qt   = 31 - (int)(blockIdx.x >> 3);  // heavy tiles first
    const int b    = blockIdx.x & 7;
    const int q0   = qt * 64;

    // ---- load Q (tf32) into chunked smem ----
    {
        const float* Qg = g_Q + ((size_t)b * Tn + q0) * Hn;
        for (int i4 = t; i4 < 1024; i4 += 128) {
            int row = i4 >> 4, u4 = i4 & 15;
            float4 v = *(const float4*)&Qg[row * Hn + u4 * 4];
            int kc = u4 >> 2, k4 = u4 & 3;
            float* base = &Ps[kc * 1024];
            float av[4] = {v.x, v.y, v.z, v.w};
#pragma unroll
            for (int e = 0; e < 4; ++e) base[swz(row, e, k4)] = f2tf(av[e]);
        }
    }
    __syncthreads();

    const int rA = warp * 16 + g;   // local query row
    const int rB = rA + 8;

    // ---- extract Q a-fragments (8 k-steps) into registers ----
    unsigned qA[8][4];
#pragma unroll
    for (int kc = 0; kc < 4; ++kc) {
        float4 lo = *(const float4*)&Ps[kc * 1024 + swz(rA, q4, 0)];
        float4 hi = *(const float4*)&Ps[kc * 1024 + swz(rB, q4, 0)];
        qA[2*kc][0]   = __float_as_uint(lo.x); qA[2*kc][1]   = __float_as_uint(hi.x);
        qA[2*kc][2]   = __float_as_uint(lo.y); qA[2*kc][3]   = __float_as_uint(hi.y);
        qA[2*kc+1][0] = __float_as_uint(lo.z); qA[2*kc+1][1] = __float_as_uint(hi.z);
        qA[2*kc+1][2] = __float_as_uint(lo.w); qA[2*kc+1][3] = __float_as_uint(hi.w);
    }

    float O[8][4];
#pragma unroll
    for (int j = 0; j < 8; ++j)
#pragma unroll
        for (int e = 0; e < 4; ++e) O[j][e] = 0.f;
    float mA = -1e30f, mB = -1e30f, lA = 0.f, lB = 0.f;

    for (int jt = 0; jt <= qt; ++jt) {
        __syncthreads();   // prior iter's smem reads (K,V,P) complete

        // ---- load K tile (direct) + V tile (transposed) ----
        {
            const float* Kg = g_K + ((size_t)b * Tn + jt * 64) * Hn;
            const float* Vg = g_V + ((size_t)b * Tn + jt * 64) * Hn;
            for (int i4 = t; i4 < 1024; i4 += 128) {
                int row = i4 >> 4, u4 = i4 & 15;
                float4 v = *(const float4*)&Kg[row * Hn + u4 * 4];
                int kc = u4 >> 2, k4 = u4 & 3;
                float* base = &Ks[kc * 1024];
                float av[4] = {v.x, v.y, v.z, v.w};
#pragma unroll
                for (int e = 0; e < 4; ++e) base[swz(row, e, k4)] = f2tf(av[e]);
            }
            for (int i4 = t; i4 < 1024; i4 += 128) {
                int key = i4 >> 4, u4 = i4 & 15;
                float4 v = *(const float4*)&Vg[key * Hn + u4 * 4];
                int kc = key >> 4, c4 = key & 3, k4 = (key >> 2) & 3;
                float* base = &Vs[kc * 1024];
                float av[4] = {v.x, v.y, v.z, v.w};
#pragma unroll
                for (int e = 0; e < 4; ++e) {
                    int d = u4 * 4 + e;
                    base[swz(d, c4, k4)] = f2tf(av[e]);
                }
            }
        }
        __syncthreads();

        // ---- S = Q @ K^T ----
        float S[8][4];
#pragma unroll
        for (int j = 0; j < 8; ++j)
#pragma unroll
            for (int e = 0; e < 4; ++e) S[j][e] = 0.f;

#pragma unroll
        for (int kc = 0; kc < 4; ++kc) {
#pragma unroll
            for (int jb = 0; jb < 8; jb += 4) {
                float4 kf[4];
#pragma unroll
                for (int j = 0; j < 4; ++j) {
                    int n = 8 * (jb + j) + g;
                    kf[j] = *(const float4*)&Ks[kc * 1024 + swz(n, q4, 0)];
                }
#pragma unroll
                for (int j = 0; j < 4; ++j) {
                    int jj = jb + j;
                    mma_tf32(S[jj][0], S[jj][1], S[jj][2], S[jj][3],
                             qA[2*kc][0], qA[2*kc][1], qA[2*kc][2], qA[2*kc][3],
                             __float_as_uint(kf[j].x), __float_as_uint(kf[j].y));
                    mma_tf32(S[jj][0], S[jj][1], S[jj][2], S[jj][3],
                             qA[2*kc+1][0], qA[2*kc+1][1], qA[2*kc+1][2], qA[2*kc+1][3],
                             __float_as_uint(kf[j].z), __float_as_uint(kf[j].w));
                }
            }
        }

        // ---- causal mask on the diagonal tile ----
        if (jt == qt) {
#pragma unroll
            for (int j = 0; j < 8; ++j) {
                int c = 8 * j + 2 * q4;
                if (c     > rA) S[j][0] = -1e30f;
                if (c + 1 > rA) S[j][1] = -1e30f;
                if (c     > rB) S[j][2] = -1e30f;
                if (c + 1 > rB) S[j][3] = -1e30f;
            }
        }

        // ---- online softmax (rows rA, rB; quad reduction) ----
        float mxA = -1e30f, mxB = -1e30f;
#pragma unroll
        for (int j = 0; j < 8; ++j) {
            mxA = fmaxf(mxA, fmaxf(S[j][0], S[j][1]));
            mxB = fmaxf(mxB, fmaxf(S[j][2], S[j][3]));
        }
        mxA = fmaxf(mxA, __shfl_xor_sync(0xffffffffu, mxA, 1));
        mxA = fmaxf(mxA, __shfl_xor_sync(0xffffffffu, mxA, 2));
        mxB = fmaxf(mxB, __shfl_xor_sync(0xffffffffu, mxB, 1));
        mxB = fmaxf(mxB, __shfl_xor_sync(0xffffffffu, mxB, 2));

        float nmA = fmaxf(mA, mxA), nmB = fmaxf(mB, mxB);
        float fA = __expf(mA - nmA), fB = __expf(mB - nmB);
        mA = nmA; mB = nmB;

        float sA = 0.f, sB = 0.f;
#pragma unroll
        for (int j = 0; j < 8; ++j) {
            S[j][0] = __expf(S[j][0] - nmA); sA += S[j][0];
            S[j][1] = __expf(S[j][1] - nmA); sA += S[j][1];
            S[j][2] = __expf(S[j][2] - nmB); sB += S[j][2];
            S[j][3] = __expf(S[j][3] - nmB); sB += S[j][3];
        }
        lA = lA * fA + sA;
        lB = lB * fB + sB;
#pragma unroll
        for (int j = 0; j < 8; ++j) {
            O[j][0] *= fA; O[j][1] *= fA;
            O[j][2] *= fB; O[j][3] *= fB;
        }

        // ---- store P (tf32) into the freed Q buffer; warp-local rows ----
#pragma unroll
        for (int j = 0; j < 8; ++j) {
            int c0 = 8 * j + 2 * q4, c1 = c0 + 1;
            Ps[(c0 >> 4) * 1024 + rA * 16 + (((c0 & 3) ^ (rA & 3)) << 2) + ((c0 >> 2) & 3)] = f2tf(S[j][0]);
            Ps[(c1 >> 4) * 1024 + rA * 16 + (((c1 & 3) ^ (rA & 3)) << 2) + ((c1 >> 2) & 3)] = f2tf(S[j][1]);
            Ps[(c0 >> 4) * 1024 + rB * 16 + (((c0 & 3) ^ (rB & 3)) << 2) + ((c0 >> 2) & 3)] = f2tf(S[j][2]);
            Ps[(c1 >> 4) * 1024 + rB * 16 + (((c1 & 3) ^ (rB & 3)) << 2) + ((c1 >> 2) & 3)] = f2tf(S[j][3]);
        }
        __syncwarp();

        // ---- O += P @ V ----
#pragma unroll
        for (int kc = 0; kc < 4; ++kc) {
            float4 pLo = *(const float4*)&Ps[kc * 1024 + swz(rA, q4, 0)];
            float4 pHi = *(const float4*)&Ps[kc * 1024 + swz(rB, q4, 0)];
            unsigned a00 = __float_as_uint(pLo.x), a01 = __float_as_uint(pHi.x);
            unsigned a02 = __float_as_uint(pLo.y), a03 = __float_as_uint(pHi.y);
            unsigned a10 = __float_as_uint(pLo.z), a11 = __float_as_uint(pHi.z);
            unsigned a12 = __float_as_uint(pLo.w), a13 = __float_as_uint(pHi.w);
#pragma unroll
            for (int jb = 0; jb < 8; jb += 4) {
                float4 vf[4];
#pragma unroll
                for (int j = 0; j < 4; ++j) {
                    int n = 8 * (jb + j) + g;
                    vf[j] = *(const float4*)&Vs[kc * 1024 + swz(n, q4, 0)];
                }
#pragma unroll
                for (int j = 0; j < 4; ++j) {
                    int jj = jb + j;
                    mma_tf32(O[jj][0], O[jj][1], O[jj][2], O[jj][3],
                             a00, a01, a02, a03,
                             __float_as_uint(vf[j].x), __float_as_uint(vf[j].y));
                    mma_tf32(O[jj][0], O[jj][1], O[jj][2], O[jj][3],
                             a10, a11, a12, a13,
                             __float_as_uint(vf[j].z), __float_as_uint(vf[j].w));
                }
            }
        }
    }

    // ---- finalize ----
    lA += __shfl_xor_sync(0xffffffffu, lA, 1);
    lA += __shfl_xor_sync(0xffffffffu, lA, 2);
    lB += __shfl_xor_sync(0xffffffffu, lB, 1);
    lB += __shfl_xor_sync(0xffffffffu, lB, 2);
    float invA = 1.f / lA, invB = 1.f / lB;

    size_t rowAg = (size_t)b * Tn + q0 + rA;
    size_t rowBg = rowAg + 8;
#pragma unroll
    for (int j = 0; j < 8; ++j) {
        int c = 8 * j + 2 * q4;
        *(float2*)&out[rowAg * Hn + c] = make_float2(O[j][0] * invA, O[j][1] * invA);
        *(float2*)&out[rowBg * Hn + c] = make_float2(O[j][2] * invB, O[j][3] * invB);
    }
}

// ---------------------------------------------------------------------------
extern "C" void kernel_launch(void* const* d_in, const int* in_sizes, int n_in,
                              void* d_out, int out_size)
{
    (void)in_sizes; (void)n_in; (void)out_size;
    const float* x  = (const float*)d_in[0];
    const float* Wq = (const float*)d_in[1];
    const float* Wk = (const float*)d_in[2];
    const float* Wv = (const float*)d_in[3];
    float* out = (float*)d_out;

    qkv_mma<<<Mn / 64, 256>>>(x, Wq, Wk, Wv);
    attn_mma<<<Bn * (Tn / 64), 128>>>(out);
}